// round 3
// baseline (speedup 1.0000x reference)
#include <cuda_runtime.h>
#include <cuda_bf16.h>

// Problem constants
#define Bq 16
#define Dq 128
#define Lq 4096
#define Kq 8
#define Nq 1024

#define TM 64        // l-positions per CTA
#define NCHUNK 128   // codes per smem chunk
#define THREADS 256
#define PITCH 132    // floats per smem row (128 + 4 pad): conflict-free LDS.128

#define ZQ_ELEMS (Bq*Kq*Dq*Lq)

typedef unsigned long long u64;

// packed f32x2 fma: d = a*b + c (elementwise on 2 packed floats)
__device__ __forceinline__ u64 ffma2(u64 a, u64 b, u64 c) {
    u64 d;
    asm("fma.rn.f32x2 %0, %1, %2, %3;" : "=l"(d) : "l"(a), "l"(b), "l"(c));
    return d;
}
__device__ __forceinline__ float f2_lo(u64 v) { return __uint_as_float((unsigned)v); }
__device__ __forceinline__ float f2_hi(u64 v) { return __uint_as_float((unsigned)(v >> 32)); }

// Scratch (allocation-free rule: __device__ globals)
__device__ float g_cnorm[Kq*Nq];          // ||c||^2 per code
__device__ float g_res[Bq*Dq*Lq];         // running residual (B,D,L)

// Shared memory layout (in floats)
#define RES_OFF 0                          // resT[64 m][PITCH]   (d-minor)
#define CBS_OFF (64*PITCH)                 // cbs[128 n][PITCH]   (d-minor) / reused as sel[64 m][PITCH]
#define CN_OFF  (CBS_OFF + 128*PITCH)      // cnormS[1024]
#define RI_OFF  (CN_OFF + 1024)            // rowIdx[64] (ints)
#define SMEM_FLOATS (RI_OFF + 64)

__global__ void cnorm_kernel(const float* __restrict__ cb) {
    int gw   = (blockIdx.x * blockDim.x + threadIdx.x) >> 5;  // one warp per code
    int lane = threadIdx.x & 31;
    if (gw >= Kq * Nq) return;
    float4 v = *(const float4*)&cb[(size_t)gw * Dq + lane * 4];
    float s = v.x*v.x + v.y*v.y + v.z*v.z + v.w*v.w;
    #pragma unroll
    for (int off = 16; off > 0; off >>= 1)
        s += __shfl_xor_sync(0xffffffffu, s, off);
    if (lane == 0) g_cnorm[gw] = s;
}

__global__ void __launch_bounds__(THREADS, 2)
vq_step(const float* __restrict__ x, const float* __restrict__ cb,
        float* __restrict__ out, float* __restrict__ idxOut, int k)
{
    extern __shared__ float sm[];
    float* resT   = sm + RES_OFF;   // [64 m][PITCH]
    float* cbs    = sm + CBS_OFF;   // [128 n][PITCH]
    float* cnormS = sm + CN_OFF;    // [1024]
    int*   rowIdx = (int*)(sm + RI_OFF);

    const int tid = threadIdx.x;
    const int b   = blockIdx.y;
    const int l0  = blockIdx.x * TM;
    const int tm  = tid >> 5;   // warp id: rows 8*tm .. 8*tm+7
    const int tn  = tid & 31;   // lane:    cols tn + 32*j

    // codebook norms for this stage
    for (int i = tid; i < Nq; i += THREADS)
        cnormS[i] = g_cnorm[k * Nq + i];

    // residual tile: resT[m][d] (k==0 reads x directly; else running residual)
    {
        const float* src = (k == 0) ? x : g_res;
        #pragma unroll
        for (int it = 0; it < 32; ++it) {
            int d = it * 4 + (tid >> 6);
            int m = tid & 63;
            resT[m * PITCH + d] = src[((size_t)b * Dq + d) * Lq + l0 + m];
        }
    }
    __syncthreads();

    float bestv[8];
    int   bestn[8];
    #pragma unroll
    for (int i = 0; i < 8; ++i) { bestv[i] = 3.4e38f; bestn[i] = 0; }

    for (int chunk = 0; chunk < Nq / NCHUNK; ++chunk) {
        // load chunk of 128 code rows into cbs[n][d] (same orientation as global)
        {
            const float4* cb4 = (const float4*)
                &cb[((size_t)(k * Nq + chunk * NCHUNK)) * Dq];
            #pragma unroll
            for (int it = 0; it < 16; ++it) {
                int f   = tid + THREADS * it;   // float4 index within chunk
                int row = f >> 5;               // 32 float4 per row
                int c4  = f & 31;
                *(float4*)&cbs[row * PITCH + c4 * 4] = cb4[row * 32 + c4];
            }
        }
        __syncthreads();

        // packed accumulators: lo = even-d partial sum, hi = odd-d partial sum
        u64 acc2[8][4];
        #pragma unroll
        for (int i = 0; i < 8; ++i)
            #pragma unroll
            for (int j = 0; j < 4; ++j)
                acc2[i][j] = 0ULL;

        #pragma unroll 2
        for (int kk4 = 0; kk4 < Dq / 4; ++kk4) {
            ulonglong2 bvv[4];
            #pragma unroll
            for (int j = 0; j < 4; ++j)
                bvv[j] = *(const ulonglong2*)&cbs[(tn + 32 * j) * PITCH + kk4 * 4];
            #pragma unroll
            for (int half = 0; half < 2; ++half) {
                ulonglong2 av[4];
                #pragma unroll
                for (int ii = 0; ii < 4; ++ii)
                    av[ii] = *(const ulonglong2*)
                        &resT[(tm * 8 + half * 4 + ii) * PITCH + kk4 * 4];
                #pragma unroll
                for (int ii = 0; ii < 4; ++ii) {
                    int i = half * 4 + ii;
                    #pragma unroll
                    for (int j = 0; j < 4; ++j) {
                        acc2[i][j] = ffma2(av[ii].x, bvv[j].x, acc2[i][j]);
                        acc2[i][j] = ffma2(av[ii].y, bvv[j].y, acc2[i][j]);
                    }
                }
            }
        }

        // distances (||r||^2 dropped: constant per row) + running argmin
        #pragma unroll
        for (int j = 0; j < 4; ++j) {
            int n = chunk * NCHUNK + tn + 32 * j;
            float cn = cnormS[n];
            #pragma unroll
            for (int i = 0; i < 8; ++i) {
                float dot = f2_lo(acc2[i][j]) + f2_hi(acc2[i][j]);
                float s = cn - 2.0f * dot;
                if (s < bestv[i] || (s == bestv[i] && n < bestn[i])) {
                    bestv[i] = s; bestn[i] = n;
                }
            }
        }
        __syncthreads();   // before next chunk overwrites cbs
    }

    // warp argmin reduction (tie -> smallest n)
    #pragma unroll
    for (int i = 0; i < 8; ++i) {
        float bv = bestv[i]; int bn = bestn[i];
        #pragma unroll
        for (int off = 16; off > 0; off >>= 1) {
            float ov = __shfl_xor_sync(0xffffffffu, bv, off);
            int   on = __shfl_xor_sync(0xffffffffu, bn, off);
            if (ov < bv || (ov == bv && on < bn)) { bv = ov; bn = on; }
        }
        if (tn == 0) rowIdx[tm * 8 + i] = bn;
    }
    __syncthreads();

    // indices output (B, L, K), cast to float
    if (tid < TM)
        idxOut[((size_t)b * Lq + l0 + tid) * Kq + k] = (float)rowIdx[tid];

    // stage the 64 selected code rows into smem (reuse cbs region): sel[m][d]
    {
        #pragma unroll
        for (int rr = 0; rr < 8; ++rr) {
            int row = tm * 8 + rr;
            int idx = rowIdx[row];
            float4 v = *(const float4*)&cb[((size_t)(k * Nq + idx)) * Dq + tn * 4];
            *(float4*)&cbs[row * PITCH + tn * 4] = v;
        }
    }
    __syncthreads();

    // cumulative output + residual update, all l-coalesced
    {
        size_t outBase  = (((size_t)b * Kq + k) * Dq) * Lq;
        size_t prevBase = (k > 0) ? ((((size_t)b * Kq + (k - 1)) * Dq) * Lq) : 0;
        #pragma unroll
        for (int it = 0; it < 32; ++it) {
            int d = it * 4 + (tid >> 6);
            int m = tid & 63;
            float code = cbs[m * PITCH + d];
            float prev = (k > 0) ? out[prevBase + (size_t)d * Lq + l0 + m] : 0.0f;
            out[outBase + (size_t)d * Lq + l0 + m] = prev + code;
            g_res[((size_t)b * Dq + d) * Lq + l0 + m] = resT[m * PITCH + d] - code;
        }
    }
}

extern "C" void kernel_launch(void* const* d_in, const int* in_sizes, int n_in,
                              void* d_out, int out_size)
{
    const float* x  = (const float*)d_in[0];
    const float* cb = (const float*)d_in[1];
    float* out    = (float*)d_out;
    float* idxOut = out + (size_t)ZQ_ELEMS;

    cudaFuncSetAttribute(vq_step, cudaFuncAttributeMaxDynamicSharedMemorySize,
                         SMEM_FLOATS * 4);

    cnorm_kernel<<<(Kq * Nq * 32) / 256, 256>>>(cb);
    for (int k = 0; k < Kq; ++k)
        vq_step<<<dim3(Lq / TM, Bq), THREADS, SMEM_FLOATS * 4>>>(x, cb, out, idxOut, k);
}

// round 8
// speedup vs baseline: 1.0187x; 1.0187x over previous
#include <cuda_runtime.h>
#include <cuda_bf16.h>
#include <cstdint>

// Problem constants
#define Bq 16
#define Dq 128
#define Lq 4096
#define Kq 8
#define Nq 1024
#define ZQ_ELEMS (Bq*Kq*Dq*Lq)

#define THREADS 256
#define NCH 64
#define NCHUNKS (Nq/NCH)
#define PITCHB 272             // 136 bf16 per row (128 + 8 pad): conflict-free ldmatrix
#define A_TILE 34816           // 128 rows x PITCHB
#define B_TILE 17408           // 64 rows x PITCHB
#define B_CHUNK (3*B_TILE)     // 52224: h,m,l splits contiguous
#define B_CHUNK_F4 (B_CHUNK/16)  // 3264

// Shared memory byte offsets
#define SM_A      0            // 3 splits x A_TILE (h, m, l)
#define SM_B      104448       // 2 bufs x B_CHUNK
#define SM_CNORM  208896       // 1024 floats
#define SM_REDV   212992       // float[4][128]
#define SM_REDI   215040       // int[4][128]
#define SM_ROWIDX 217088       // int[128]
#define SMEM_BYTES 217600

// __device__ scratch (allocation-free rule)
__device__ float g_cnorm[Kq*Nq];
__device__ float g_res[Bq*Dq*Lq];
// per (k,chunk): 3 splits x 64 rows x 136 bf16, contiguous
__device__ __nv_bfloat16 g_cbs[Kq*NCHUNKS*3*64*136];

// ---------------- PTX helpers (plain sm_80-class) ----------------
__device__ __forceinline__ uint32_t s2u(const void* p) {
    uint32_t a;
    asm("{ .reg .u64 t; cvta.to.shared.u64 t, %1; cvt.u32.u64 %0, t; }" : "=r"(a) : "l"(p));
    return a;
}
#define CP16(d,s)    asm volatile("cp.async.cg.shared.global [%0], [%1], 16;" :: "r"(d), "l"(s) : "memory")
#define CP_COMMIT()  asm volatile("cp.async.commit_group;" ::: "memory")
template<int N> __device__ __forceinline__ void cp_wait() {
    asm volatile("cp.async.wait_group %0;" :: "n"(N) : "memory");
}
__device__ __forceinline__ void ldsm4(uint32_t& r0, uint32_t& r1, uint32_t& r2, uint32_t& r3,
                                      uint32_t addr) {
    asm volatile("ldmatrix.sync.aligned.m8n8.x4.shared.b16 {%0,%1,%2,%3}, [%4];"
                 : "=r"(r0), "=r"(r1), "=r"(r2), "=r"(r3) : "r"(addr));
}
__device__ __forceinline__ void mma16816(float* d, const uint32_t* a, uint32_t b0, uint32_t b1) {
    asm volatile(
        "mma.sync.aligned.m16n8k16.row.col.f32.bf16.bf16.f32 "
        "{%0,%1,%2,%3}, {%4,%5,%6,%7}, {%8,%9}, {%0,%1,%2,%3};"
        : "+f"(d[0]), "+f"(d[1]), "+f"(d[2]), "+f"(d[3])
        : "r"(a[0]), "r"(a[1]), "r"(a[2]), "r"(a[3]), "r"(b0), "r"(b1));
}

// ---------------- prep kernels ----------------
__global__ void cnorm_kernel(const float* __restrict__ cb) {
    int gw   = (blockIdx.x * blockDim.x + threadIdx.x) >> 5;
    int lane = threadIdx.x & 31;
    if (gw >= Kq * Nq) return;
    float4 v = *(const float4*)&cb[(size_t)gw * Dq + lane * 4];
    float s = v.x*v.x + v.y*v.y + v.z*v.z + v.w*v.w;
    #pragma unroll
    for (int off = 16; off > 0; off >>= 1)
        s += __shfl_xor_sync(0xffffffffu, s, off);
    if (lane == 0) g_cnorm[gw] = s;
}

// split codebook fp32 -> (h, m, l) bf16, store padded chunked images
__global__ void prep_kernel(const float* __restrict__ cb) {
    int idx = blockIdx.x * 256 + threadIdx.x;
    if (idx >= Kq * Nq * Dq) return;
    int d = idx & (Dq - 1);
    int n = (idx >> 7) & (Nq - 1);
    int k = idx >> 17;
    float v = cb[idx];
    __nv_bfloat16 h = __float2bfloat16(v);
    float r1 = v - __bfloat162float(h);
    __nv_bfloat16 m = __float2bfloat16(r1);
    __nv_bfloat16 l = __float2bfloat16(r1 - __bfloat162float(m));
    size_t base = ((size_t)(k * NCHUNKS + (n >> 6)) * 3) * 8704 + (size_t)(n & 63) * 136 + d;
    g_cbs[base]            = h;
    g_cbs[base + 8704]     = m;
    g_cbs[base + 2 * 8704] = l;
}

// ---------------- main stage kernel ----------------
__device__ __forceinline__ void prefetchB(int k, int c, uint32_t dst, int tid) {
    const char* src = (const char*)g_cbs + (size_t)(k * NCHUNKS + c) * B_CHUNK;
    #pragma unroll
    for (int j = 0; j < 13; ++j) {
        int f4 = tid + j * THREADS;
        if (f4 < B_CHUNK_F4) {
            uint32_t o = (uint32_t)f4 * 16u;
            CP16(dst + o, src + o);
        }
    }
}

__global__ void __launch_bounds__(THREADS, 1)
vq_step(const float* __restrict__ x, const float* __restrict__ cb,
        float* __restrict__ out, float* __restrict__ idxOut, int k)
{
    extern __shared__ char smem[];
    const uint32_t sb = s2u(smem);
    const int tid  = threadIdx.x;
    const int wid  = tid >> 5;
    const int lane = tid & 31;
    const int b    = blockIdx.y;
    const int l0   = blockIdx.x * 128;
    const int wm   = wid >> 2;          // 0..1 : m half (64 rows)
    const int wn   = wid & 3;           // 0..3 : n quarter (16 cols)
    const int mb   = wm * 64;
    const int nb   = wn * 16;

    float* cnormS = (float*)(smem + SM_CNORM);
    float* redv   = (float*)(smem + SM_REDV);
    int*   redi   = (int*)  (smem + SM_REDI);
    int*   rowIdx = (int*)  (smem + SM_ROWIDX);

    for (int i = tid; i < Nq; i += THREADS)
        cnormS[i] = g_cnorm[k * Nq + i];

    // A tiles: residual (128 l x 128 d) -> 3 bf16 splits, pitch 136
    {
        const float* src = (k == 0) ? x : g_res;
        const size_t base = ((size_t)b * Dq) * Lq + l0;
        #pragma unroll
        for (int i = 0; i < 16; ++i) {
            int q  = tid + THREADS * i;       // 4096 float4
            int d  = q >> 5;
            int l4 = q & 31;
            float4 v = *(const float4*)&src[base + (size_t)d * Lq + l4 * 4];
            float vv[4] = {v.x, v.y, v.z, v.w};
            #pragma unroll
            for (int e = 0; e < 4; ++e) {
                int l = l4 * 4 + e;
                float val = vv[e];
                __nv_bfloat16 h = __float2bfloat16(val);
                float r1 = val - __bfloat162float(h);
                __nv_bfloat16 m = __float2bfloat16(r1);
                __nv_bfloat16 lo = __float2bfloat16(r1 - __bfloat162float(m));
                uint32_t o = (uint32_t)(l * PITCHB + d * 2);
                *(__nv_bfloat16*)(smem + SM_A + o)              = h;
                *(__nv_bfloat16*)(smem + SM_A + A_TILE + o)     = m;
                *(__nv_bfloat16*)(smem + SM_A + 2 * A_TILE + o) = lo;
            }
        }
    }

    // prefetch B chunks 0, 1
    prefetchB(k, 0, sb + SM_B, tid);           CP_COMMIT();
    prefetchB(k, 1, sb + SM_B + B_CHUNK, tid); CP_COMMIT();

    // ldmatrix lane offsets (validated mappings from Round 6)
    const int grp = lane >> 3, win = lane & 7;
    const uint32_t aLaneOff = (uint32_t)((win + (grp & 1) * 8) * PITCHB + ((grp >> 1) * 8) * 2);
    const uint32_t bLaneOff = (uint32_t)((win + (grp >> 1) * 8) * PITCHB + ((grp & 1) * 8) * 2);
    const int r4 = lane >> 2, c2 = (lane & 3) * 2;

    float bestv[8];
    int   bestn[8];
    #pragma unroll
    for (int s = 0; s < 8; ++s) { bestv[s] = 3.4e38f; bestn[s] = 0; }

    for (int c = 0; c < NCHUNKS; ++c) {
        cp_wait<1>();
        __syncthreads();
        const uint32_t bufOff = SM_B + (uint32_t)((c & 1) ? B_CHUNK : 0);

        float acc[4][2][4];
        #pragma unroll
        for (int f = 0; f < 4; ++f)
            #pragma unroll
            for (int j = 0; j < 2; ++j)
                #pragma unroll
                for (int e = 0; e < 4; ++e) acc[f][j][e] = 0.0f;

        // combos grouped by A split (0=h,1=m,2=l), issued small-terms-first:
        //   a=l: b={h};  a=m: b={m,h};  a=h: b={l,m,h}
        #pragma unroll
        for (int ai = 0; ai < 3; ++ai) {
            const int a  = 2 - ai;
            const int nB = ai + 1;
            const uint32_t aB = sb + SM_A + (uint32_t)a * A_TILE
                                + (uint32_t)(mb * PITCHB) + aLaneOff;
            #pragma unroll
            for (int ks = 0; ks < 8; ++ks) {
                uint32_t af[4][4];
                #pragma unroll
                for (int f = 0; f < 4; ++f)
                    ldsm4(af[f][0], af[f][1], af[f][2], af[f][3],
                          aB + (uint32_t)(f * 16 * PITCHB + ks * 32));
                #pragma unroll
                for (int bi = 0; bi < nB; ++bi) {
                    const int bsp = nB - 1 - bi;
                    const uint32_t bB = sb + bufOff + (uint32_t)bsp * B_TILE
                                        + (uint32_t)(nb * PITCHB) + bLaneOff;
                    uint32_t bq[4];
                    ldsm4(bq[0], bq[1], bq[2], bq[3], bB + (uint32_t)(ks * 32));
                    #pragma unroll
                    for (int f = 0; f < 4; ++f) {
                        mma16816(acc[f][0], af[f], bq[0], bq[1]);
                        mma16816(acc[f][1], af[f], bq[2], bq[3]);
                    }
                }
            }
        }

        // distances + running argmin (ascending n; strict < keeps smallest)
        #pragma unroll
        for (int j = 0; j < 2; ++j)
            #pragma unroll
            for (int e = 0; e < 2; ++e) {
                const int n = c * NCH + nb + j * 8 + c2 + e;
                const float cnv = cnormS[n];
                #pragma unroll
                for (int f = 0; f < 4; ++f)
                    #pragma unroll
                    for (int hh = 0; hh < 2; ++hh) {
                        float s = cnv - 2.0f * acc[f][j][hh * 2 + e];
                        int slot = f * 2 + hh;
                        if (s < bestv[slot]) { bestv[slot] = s; bestn[slot] = n; }
                    }
            }

        __syncthreads();                 // all reads of buf done before overwrite
        if (c + 2 < NCHUNKS)
            prefetchB(k, c + 2, sb + SM_B + (uint32_t)((c & 1) ? B_CHUNK : 0), tid);
        CP_COMMIT();                     // always commit (group accounting)
    }

    // cross-lane reduce within 4-lane column groups, stage per-warp results
    #pragma unroll
    for (int s = 0; s < 8; ++s) {
        float v = bestv[s]; int n = bestn[s];
        #pragma unroll
        for (int off = 1; off <= 2; off <<= 1) {
            float ov = __shfl_xor_sync(0xffffffffu, v, off);
            int   on = __shfl_xor_sync(0xffffffffu, n, off);
            if (ov < v || (ov == v && on < n)) { v = ov; n = on; }
        }
        if ((lane & 3) == 0) {
            int row = mb + (s >> 1) * 16 + (s & 1) * 8 + r4;
            redv[wn * 128 + row] = v;
            redi[wn * 128 + row] = n;
        }
    }
    __syncthreads();

    // final reduce over the 4 n-warps; write indices
    if (tid < 128) {
        float bv = redv[tid]; int bn = redi[tid];
        #pragma unroll
        for (int w = 1; w < 4; ++w) {
            float v = redv[w * 128 + tid]; int n = redi[w * 128 + tid];
            if (v < bv || (v == bv && n < bn)) { bv = v; bn = n; }
        }
        rowIdx[tid] = bn;
        idxOut[((size_t)b * Lq + l0 + tid) * Kq + k] = (float)bn;
    }
    __syncthreads();

    // gather selected fp32 code rows into smem (reuse B region): sel[128][132]
    float* sel = (float*)(smem + SM_B);
    #pragma unroll
    for (int i = 0; i < 16; ++i) {
        int row = wid * 16 + i;
        int idx = rowIdx[row];
        float4 v = *(const float4*)&cb[((size_t)(k * Nq + idx)) * Dq + lane * 4];
        *(float4*)&sel[row * 132 + lane * 4] = v;
    }
    __syncthreads();

    // cumulative output + residual update (coalesced over l)
    {
        const int lR = tid & 127;
        const int d0 = (tid >> 7) * 64;
        size_t outBase  = (((size_t)b * Kq + k) * Dq) * Lq + l0 + lR;
        size_t prevBase = (((size_t)b * Kq + (k - 1)) * Dq) * Lq + l0 + lR;
        size_t resBase  = ((size_t)b * Dq) * Lq + l0 + lR;
        #pragma unroll 4
        for (int dd = 0; dd < 64; ++dd) {
            int d = d0 + dd;
            float code = sel[lR * 132 + d];
            float prev = (k > 0) ? out[prevBase + (size_t)d * Lq] : 0.0f;
            out[outBase + (size_t)d * Lq] = prev + code;
            float ro = (k == 0) ? x[resBase + (size_t)d * Lq]
                                : g_res[resBase + (size_t)d * Lq];
            g_res[resBase + (size_t)d * Lq] = ro - code;
        }
    }
}

extern "C" void kernel_launch(void* const* d_in, const int* in_sizes, int n_in,
                              void* d_out, int out_size)
{
    const float* x  = (const float*)d_in[0];
    const float* cb = (const float*)d_in[1];
    float* out    = (float*)d_out;
    float* idxOut = out + (size_t)ZQ_ELEMS;

    cudaFuncSetAttribute(vq_step, cudaFuncAttributeMaxDynamicSharedMemorySize, SMEM_BYTES);

    cnorm_kernel<<<(Kq * Nq * 32) / 256, 256>>>(cb);
    prep_kernel<<<(Kq * Nq * Dq) / 256, 256>>>(cb);
    for (int k = 0; k < Kq; ++k)
        vq_step<<<dim3(Lq / 128, Bq), THREADS, SMEM_BYTES>>>(x, cb, out, idxOut, k);
}

// round 9
// speedup vs baseline: 1.8201x; 1.7867x over previous
#include <cuda_runtime.h>
#include <cuda_fp16.h>
#include <cstdint>

// Problem constants
#define Bq 16
#define Dq 128
#define Lq 4096
#define Kq 8
#define Nq 1024
#define ZQ_ELEMS (Bq*Kq*Dq*Lq)

#define THREADS 512
#define NCH 64
#define NCHUNKS (Nq/NCH)
#define PITCHB 272             // 136 fp16 per row (128 + 8 pad): conflict-free ldmatrix
#define A_TILE 34816           // 128 rows x PITCHB
#define B_TILE 17408           // 64 rows x PITCHB
#define B_CHUNK (2*B_TILE)     // 34816: h,m splits contiguous
#define B_CHUNK_F4 (B_CHUNK/16)  // 2176

// Shared memory byte offsets
#define SM_A      0            // 2 splits x A_TILE (h, m)
#define SM_B      69632        // 2 bufs x B_CHUNK
#define SM_CNORM  139264       // 1024 floats
#define SM_REDV   143360       // float[4][128]
#define SM_REDI   145408       // int[4][128]
#define SM_ROWIDX 147456       // int[128]
#define SMEM_BYTES 148224

// __device__ scratch (allocation-free rule)
__device__ float g_cnorm[Kq*Nq];
__device__ float g_res[Bq*Dq*Lq];
// per (k,chunk): 2 splits x 64 rows x 136 fp16, contiguous
__device__ __half g_cbs[Kq*NCHUNKS*2*64*136];

// ---------------- PTX helpers (plain sm_80-class) ----------------
__device__ __forceinline__ uint32_t s2u(const void* p) {
    uint32_t a;
    asm("{ .reg .u64 t; cvta.to.shared.u64 t, %1; cvt.u32.u64 %0, t; }" : "=r"(a) : "l"(p));
    return a;
}
#define CP16(d,s)    asm volatile("cp.async.cg.shared.global [%0], [%1], 16;" :: "r"(d), "l"(s) : "memory")
#define CP_COMMIT()  asm volatile("cp.async.commit_group;" ::: "memory")
template<int N> __device__ __forceinline__ void cp_wait() {
    asm volatile("cp.async.wait_group %0;" :: "n"(N) : "memory");
}
__device__ __forceinline__ void ldsm4(uint32_t& r0, uint32_t& r1, uint32_t& r2, uint32_t& r3,
                                      uint32_t addr) {
    asm volatile("ldmatrix.sync.aligned.m8n8.x4.shared.b16 {%0,%1,%2,%3}, [%4];"
                 : "=r"(r0), "=r"(r1), "=r"(r2), "=r"(r3) : "r"(addr));
}
__device__ __forceinline__ void mma16816(float* d, const uint32_t* a, uint32_t b0, uint32_t b1) {
    asm volatile(
        "mma.sync.aligned.m16n8k16.row.col.f32.f16.f16.f32 "
        "{%0,%1,%2,%3}, {%4,%5,%6,%7}, {%8,%9}, {%0,%1,%2,%3};"
        : "+f"(d[0]), "+f"(d[1]), "+f"(d[2]), "+f"(d[3])
        : "r"(a[0]), "r"(a[1]), "r"(a[2]), "r"(a[3]), "r"(b0), "r"(b1));
}

// ---------------- prep kernels ----------------
__global__ void cnorm_kernel(const float* __restrict__ cb) {
    int gw   = (blockIdx.x * blockDim.x + threadIdx.x) >> 5;
    int lane = threadIdx.x & 31;
    if (gw >= Kq * Nq) return;
    float4 v = *(const float4*)&cb[(size_t)gw * Dq + lane * 4];
    float s = v.x*v.x + v.y*v.y + v.z*v.z + v.w*v.w;
    #pragma unroll
    for (int off = 16; off > 0; off >>= 1)
        s += __shfl_xor_sync(0xffffffffu, s, off);
    if (lane == 0) g_cnorm[gw] = s;
}

// split codebook fp32 -> (h, m) fp16, store padded chunked images
__global__ void prep_kernel(const float* __restrict__ cb) {
    int idx = blockIdx.x * 256 + threadIdx.x;
    if (idx >= Kq * Nq * Dq) return;
    int d = idx & (Dq - 1);
    int n = (idx >> 7) & (Nq - 1);
    int k = idx >> 17;
    float v = cb[idx];
    __half h = __float2half(v);
    __half m = __float2half(v - __half2float(h));
    size_t base = ((size_t)(k * NCHUNKS + (n >> 6)) * 2) * 8704 + (size_t)(n & 63) * 136 + d;
    g_cbs[base]        = h;
    g_cbs[base + 8704] = m;
}

// ---------------- main stage kernel ----------------
__device__ __forceinline__ void prefetchB(int k, int c, uint32_t dst, int tid) {
    const char* src = (const char*)g_cbs + (size_t)(k * NCHUNKS + c) * B_CHUNK;
    #pragma unroll
    for (int j = 0; j < 5; ++j) {
        int f4 = tid + j * THREADS;
        if (f4 < B_CHUNK_F4) {
            uint32_t o = (uint32_t)f4 * 16u;
            CP16(dst + o, src + o);
        }
    }
}

__global__ void __launch_bounds__(THREADS, 1)
vq_step(const float* __restrict__ x, const float* __restrict__ cb,
        float* __restrict__ out, float* __restrict__ idxOut, int k)
{
    extern __shared__ char smem[];
    const uint32_t sb = s2u(smem);
    const int tid  = threadIdx.x;
    const int wid  = tid >> 5;
    const int lane = tid & 31;
    const int b    = blockIdx.y;
    const int l0   = blockIdx.x * 128;
    const int wm   = wid >> 2;          // 0..3 : m quarter (32 rows)
    const int wn   = wid & 3;           // 0..3 : n quarter (16 cols)
    const int mb   = wm * 32;
    const int nb   = wn * 16;

    float* cnormS = (float*)(smem + SM_CNORM);
    float* redv   = (float*)(smem + SM_REDV);
    int*   redi   = (int*)  (smem + SM_REDI);
    int*   rowIdx = (int*)  (smem + SM_ROWIDX);

    for (int i = tid; i < Nq; i += THREADS)
        cnormS[i] = g_cnorm[k * Nq + i];

    // A tiles: residual (128 l x 128 d) -> 2 fp16 splits, pitch 136
    {
        const float* src = (k == 0) ? x : g_res;
        const size_t base = ((size_t)b * Dq) * Lq + l0;
        #pragma unroll
        for (int i = 0; i < 8; ++i) {
            int q  = tid + THREADS * i;       // 4096 float4
            int d  = q >> 5;
            int l4 = q & 31;
            float4 v = *(const float4*)&src[base + (size_t)d * Lq + l4 * 4];
            float vv[4] = {v.x, v.y, v.z, v.w};
            #pragma unroll
            for (int e = 0; e < 4; ++e) {
                int l = l4 * 4 + e;
                float val = vv[e];
                __half h = __float2half(val);
                __half m = __float2half(val - __half2float(h));
                uint32_t o = (uint32_t)(l * PITCHB + d * 2);
                *(__half*)(smem + SM_A + o)          = h;
                *(__half*)(smem + SM_A + A_TILE + o) = m;
            }
        }
    }

    // prefetch B chunks 0, 1
    prefetchB(k, 0, sb + SM_B, tid);           CP_COMMIT();
    prefetchB(k, 1, sb + SM_B + B_CHUNK, tid); CP_COMMIT();

    // ldmatrix lane offsets (validated in Rounds 6/8)
    const int grp = lane >> 3, win = lane & 7;
    const uint32_t aLaneOff = (uint32_t)((win + (grp & 1) * 8) * PITCHB + ((grp >> 1) * 8) * 2);
    const uint32_t bLaneOff = (uint32_t)((win + (grp >> 1) * 8) * PITCHB + ((grp & 1) * 8) * 2);
    const int r4 = lane >> 2, c2 = (lane & 3) * 2;

    float bestv[4];
    int   bestn[4];
    #pragma unroll
    for (int s = 0; s < 4; ++s) { bestv[s] = 3.4e38f; bestn[s] = 0; }

    for (int c = 0; c < NCHUNKS; ++c) {
        cp_wait<1>();
        __syncthreads();
        const uint32_t bufOff = SM_B + (uint32_t)((c & 1) ? B_CHUNK : 0);

        float acc[2][2][4];
        #pragma unroll
        for (int f = 0; f < 2; ++f)
            #pragma unroll
            for (int j = 0; j < 2; ++j)
                #pragma unroll
                for (int e = 0; e < 4; ++e) acc[f][j][e] = 0.0f;

        const uint32_t aHB = sb + SM_A +            (uint32_t)(mb * PITCHB) + aLaneOff;
        const uint32_t aMB = sb + SM_A + A_TILE +   (uint32_t)(mb * PITCHB) + aLaneOff;
        const uint32_t bHB = sb + bufOff +          (uint32_t)(nb * PITCHB) + bLaneOff;
        const uint32_t bMB = sb + bufOff + B_TILE + (uint32_t)(nb * PITCHB) + bLaneOff;

        #pragma unroll
        for (int ks = 0; ks < 8; ++ks) {
            const uint32_t ko = (uint32_t)(ks * 32);
            uint32_t ah[2][4], am[2][4], bh[4], bm[4];
            #pragma unroll
            for (int f = 0; f < 2; ++f) {
                ldsm4(ah[f][0], ah[f][1], ah[f][2], ah[f][3],
                      aHB + (uint32_t)(f * 16 * PITCHB) + ko);
                ldsm4(am[f][0], am[f][1], am[f][2], am[f][3],
                      aMB + (uint32_t)(f * 16 * PITCHB) + ko);
            }
            ldsm4(bh[0], bh[1], bh[2], bh[3], bHB + ko);
            ldsm4(bm[0], bm[1], bm[2], bm[3], bMB + ko);

            #pragma unroll
            for (int f = 0; f < 2; ++f) {
                // h*m'
                mma16816(acc[f][0], ah[f], bm[0], bm[1]);
                mma16816(acc[f][1], ah[f], bm[2], bm[3]);
                // m*h'
                mma16816(acc[f][0], am[f], bh[0], bh[1]);
                mma16816(acc[f][1], am[f], bh[2], bh[3]);
                // h*h'
                mma16816(acc[f][0], ah[f], bh[0], bh[1]);
                mma16816(acc[f][1], ah[f], bh[2], bh[3]);
            }
        }

        // distances + running argmin (ascending n; strict < keeps smallest)
        #pragma unroll
        for (int j = 0; j < 2; ++j)
            #pragma unroll
            for (int e = 0; e < 2; ++e) {
                const int n = c * NCH + nb + j * 8 + c2 + e;
                const float cnv = cnormS[n];
                #pragma unroll
                for (int f = 0; f < 2; ++f)
                    #pragma unroll
                    for (int hh = 0; hh < 2; ++hh) {
                        float s = cnv - 2.0f * acc[f][j][hh * 2 + e];
                        int slot = f * 2 + hh;
                        if (s < bestv[slot]) { bestv[slot] = s; bestn[slot] = n; }
                    }
            }

        __syncthreads();                 // all reads of buf done before overwrite
        if (c + 2 < NCHUNKS)
            prefetchB(k, c + 2, sb + SM_B + (uint32_t)((c & 1) ? B_CHUNK : 0), tid);
        CP_COMMIT();                     // always commit (group accounting)
    }

    // cross-lane reduce within 4-lane column groups, stage per-warp results
    #pragma unroll
    for (int s = 0; s < 4; ++s) {
        float v = bestv[s]; int n = bestn[s];
        #pragma unroll
        for (int off = 1; off <= 2; off <<= 1) {
            float ov = __shfl_xor_sync(0xffffffffu, v, off);
            int   on = __shfl_xor_sync(0xffffffffu, n, off);
            if (ov < v || (ov == v && on < n)) { v = ov; n = on; }
        }
        if ((lane & 3) == 0) {
            int row = mb + (s >> 1) * 16 + (s & 1) * 8 + r4;   // f*16 + hh*8 + r4
            redv[wn * 128 + row] = v;
            redi[wn * 128 + row] = n;
        }
    }
    __syncthreads();

    // final reduce over the 4 n-warps; write indices
    if (tid < 128) {
        float bv = redv[tid]; int bn = redi[tid];
        #pragma unroll
        for (int w = 1; w < 4; ++w) {
            float v = redv[w * 128 + tid]; int n = redi[w * 128 + tid];
            if (v < bv || (v == bv && n < bn)) { bv = v; bn = n; }
        }
        rowIdx[tid] = bn;
        idxOut[((size_t)b * Lq + l0 + tid) * Kq + k] = (float)bn;
    }
    __syncthreads();

    // gather selected fp32 code rows into smem (reuse B region): sel[128][132]
    float* sel = (float*)(smem + SM_B);
    #pragma unroll
    for (int i = 0; i < 8; ++i) {
        int row = wid * 8 + i;
        int idx = rowIdx[row];
        float4 v = *(const float4*)&cb[((size_t)(k * Nq + idx)) * Dq + lane * 4];
        *(float4*)&sel[row * 132 + lane * 4] = v;
    }
    __syncthreads();

    // cumulative output + residual update (coalesced over l)
    {
        const int lR = tid & 127;
        const int d0 = (tid >> 7) * 32;
        size_t outBase  = (((size_t)b * Kq + k) * Dq) * Lq + l0 + lR;
        size_t prevBase = (((size_t)b * Kq + (k - 1)) * Dq) * Lq + l0 + lR;
        size_t resBase  = ((size_t)b * Dq) * Lq + l0 + lR;
        #pragma unroll 4
        for (int dd = 0; dd < 32; ++dd) {
            int d = d0 + dd;
            float code = sel[lR * 132 + d];
            float prev = (k > 0) ? out[prevBase + (size_t)d * Lq] : 0.0f;
            out[outBase + (size_t)d * Lq] = prev + code;
            float ro = (k == 0) ? x[resBase + (size_t)d * Lq]
                                : g_res[resBase + (size_t)d * Lq];
            g_res[resBase + (size_t)d * Lq] = ro - code;
        }
    }
}

extern "C" void kernel_launch(void* const* d_in, const int* in_sizes, int n_in,
                              void* d_out, int out_size)
{
    const float* x  = (const float*)d_in[0];
    const float* cb = (const float*)d_in[1];
    float* out    = (float*)d_out;
    float* idxOut = out + (size_t)ZQ_ELEMS;

    cudaFuncSetAttribute(vq_step, cudaFuncAttributeMaxDynamicSharedMemorySize, SMEM_BYTES);

    cnorm_kernel<<<(Kq * Nq * 32) / 256, 256>>>(cb);
    prep_kernel<<<(Kq * Nq * Dq) / 256, 256>>>(cb);
    for (int k = 0; k < Kq; ++k)
        vq_step<<<dim3(Lq / 128, Bq), THREADS, SMEM_BYTES>>>(x, cb, out, idxOut, k);
}

// round 10
// speedup vs baseline: 1.8908x; 1.0388x over previous
#include <cuda_runtime.h>
#include <cuda_fp16.h>
#include <cstdint>

// Problem constants
#define Bq 16
#define Dq 128
#define Lq 4096
#define Kq 8
#define Nq 1024
#define ZQ_ELEMS (Bq*Kq*Dq*Lq)

#define THREADS 512
#define NCH 128
#define NCHUNKS (Nq/NCH)
#define PITCHB 272             // 136 fp16 per row (128 + 8 pad): conflict-free ldmatrix
#define A_TILE 34816           // 128 rows x PITCHB
#define B_TILE 34816           // 128 rows x PITCHB
#define B_CHUNK (2*B_TILE)     // 69632: h,m splits contiguous
#define B_CHUNK_F4 (B_CHUNK/16)  // 4352

// Shared memory byte offsets
#define SM_A      0            // 2 splits x A_TILE (h, m)
#define SM_B      69632        // 2 bufs x B_CHUNK
#define SM_CNORM  208896       // 1024 floats
#define SM_REDV   212992       // float[4][128]
#define SM_REDI   215040       // int[4][128]
#define SM_ROWIDX 217088       // int[128]
#define SMEM_BYTES 217600

// __device__ scratch (allocation-free rule)
__device__ float g_cnorm[Kq*Nq];
__device__ float g_res[Bq*Dq*Lq];
// per (k,chunk): 2 splits x 128 rows x 136 fp16, contiguous
__device__ __half g_cbs[Kq*NCHUNKS*2*128*136];

// ---------------- PTX helpers (plain sm_80-class) ----------------
__device__ __forceinline__ uint32_t s2u(const void* p) {
    uint32_t a;
    asm("{ .reg .u64 t; cvta.to.shared.u64 t, %1; cvt.u32.u64 %0, t; }" : "=r"(a) : "l"(p));
    return a;
}
#define CP16(d,s)    asm volatile("cp.async.cg.shared.global [%0], [%1], 16;" :: "r"(d), "l"(s) : "memory")
#define CP_COMMIT()  asm volatile("cp.async.commit_group;" ::: "memory")
template<int N> __device__ __forceinline__ void cp_wait() {
    asm volatile("cp.async.wait_group %0;" :: "n"(N) : "memory");
}
__device__ __forceinline__ void ldsm4(uint32_t& r0, uint32_t& r1, uint32_t& r2, uint32_t& r3,
                                      uint32_t addr) {
    asm volatile("ldmatrix.sync.aligned.m8n8.x4.shared.b16 {%0,%1,%2,%3}, [%4];"
                 : "=r"(r0), "=r"(r1), "=r"(r2), "=r"(r3) : "r"(addr));
}
__device__ __forceinline__ void mma16816(float* d, const uint32_t* a, uint32_t b0, uint32_t b1) {
    asm volatile(
        "mma.sync.aligned.m16n8k16.row.col.f32.f16.f16.f32 "
        "{%0,%1,%2,%3}, {%4,%5,%6,%7}, {%8,%9}, {%0,%1,%2,%3};"
        : "+f"(d[0]), "+f"(d[1]), "+f"(d[2]), "+f"(d[3])
        : "r"(a[0]), "r"(a[1]), "r"(a[2]), "r"(a[3]), "r"(b0), "r"(b1));
}

// ---------------- prep kernels ----------------
__global__ void cnorm_kernel(const float* __restrict__ cb) {
    int gw   = (blockIdx.x * blockDim.x + threadIdx.x) >> 5;
    int lane = threadIdx.x & 31;
    if (gw >= Kq * Nq) return;
    float4 v = *(const float4*)&cb[(size_t)gw * Dq + lane * 4];
    float s = v.x*v.x + v.y*v.y + v.z*v.z + v.w*v.w;
    #pragma unroll
    for (int off = 16; off > 0; off >>= 1)
        s += __shfl_xor_sync(0xffffffffu, s, off);
    if (lane == 0) g_cnorm[gw] = s;
}

// split codebook fp32 -> (h, m) fp16, store padded chunked images
__global__ void prep_kernel(const float* __restrict__ cb) {
    int idx = blockIdx.x * 256 + threadIdx.x;
    if (idx >= Kq * Nq * Dq) return;
    int d = idx & (Dq - 1);
    int n = (idx >> 7) & (Nq - 1);
    int k = idx >> 17;
    float v = cb[idx];
    __half h = __float2half(v);
    __half m = __float2half(v - __half2float(h));
    size_t base = ((size_t)(k * NCHUNKS + (n >> 7)) * 2) * 17408 + (size_t)(n & 127) * 136 + d;
    g_cbs[base]         = h;
    g_cbs[base + 17408] = m;
}

// ---------------- main stage kernel ----------------
__device__ __forceinline__ void prefetchB(int k, int c, uint32_t dst, int tid) {
    const char* src = (const char*)g_cbs + (size_t)(k * NCHUNKS + c) * B_CHUNK;
    #pragma unroll
    for (int j = 0; j < 9; ++j) {
        int f4 = tid + j * THREADS;
        if (f4 < B_CHUNK_F4) {
            uint32_t o = (uint32_t)f4 * 16u;
            CP16(dst + o, src + o);
        }
    }
}

__global__ void __launch_bounds__(THREADS, 1)
vq_step(const float* __restrict__ x, const float* __restrict__ cb,
        float* __restrict__ out, float* __restrict__ idxOut, int k)
{
    extern __shared__ char smem[];
    const uint32_t sb = s2u(smem);
    const int tid  = threadIdx.x;
    const int wid  = tid >> 5;
    const int lane = tid & 31;
    const int b    = blockIdx.y;
    const int l0   = blockIdx.x * 128;
    const int wm   = wid >> 2;          // 0..3 : m quarter (32 rows)
    const int wn   = wid & 3;           // 0..3 : n quarter (32 cols)
    const int mb   = wm * 32;
    const int nb   = wn * 32;

    float* cnormS = (float*)(smem + SM_CNORM);
    float* redv   = (float*)(smem + SM_REDV);
    int*   redi   = (int*)  (smem + SM_REDI);
    int*   rowIdx = (int*)  (smem + SM_ROWIDX);

    for (int i = tid; i < Nq; i += THREADS)
        cnormS[i] = g_cnorm[k * Nq + i];

    // A tiles: residual (128 l x 128 d) -> 2 fp16 splits, pitch 136
    {
        const float* src = (k == 0) ? x : g_res;
        const size_t base = ((size_t)b * Dq) * Lq + l0;
        #pragma unroll
        for (int i = 0; i < 8; ++i) {
            int q  = tid + THREADS * i;       // 4096 float4
            int d  = q >> 5;
            int l4 = q & 31;
            float4 v = *(const float4*)&src[base + (size_t)d * Lq + l4 * 4];
            float vv[4] = {v.x, v.y, v.z, v.w};
            #pragma unroll
            for (int e = 0; e < 4; ++e) {
                int l = l4 * 4 + e;
                float val = vv[e];
                __half h = __float2half(val);
                __half m = __float2half(val - __half2float(h));
                uint32_t o = (uint32_t)(l * PITCHB + d * 2);
                *(__half*)(smem + SM_A + o)          = h;
                *(__half*)(smem + SM_A + A_TILE + o) = m;
            }
        }
    }

    // prefetch B chunks 0, 1
    prefetchB(k, 0, sb + SM_B, tid);           CP_COMMIT();
    prefetchB(k, 1, sb + SM_B + B_CHUNK, tid); CP_COMMIT();

    // ldmatrix lane offsets (validated in Rounds 6/8/9)
    const int grp = lane >> 3, win = lane & 7;
    const uint32_t aLaneOff = (uint32_t)((win + (grp & 1) * 8) * PITCHB + ((grp >> 1) * 8) * 2);
    const uint32_t bLaneOff = (uint32_t)((win + (grp >> 1) * 8) * PITCHB + ((grp & 1) * 8) * 2);
    const int r4 = lane >> 2, c2 = (lane & 3) * 2;

    float bestv[4];
    int   bestn[4];
    #pragma unroll
    for (int s = 0; s < 4; ++s) { bestv[s] = 3.4e38f; bestn[s] = 0; }

    for (int c = 0; c < NCHUNKS; ++c) {
        cp_wait<1>();
        __syncthreads();
        const uint32_t bufOff = SM_B + (uint32_t)((c & 1) ? B_CHUNK : 0);

        float acc[2][4][4];
        #pragma unroll
        for (int f = 0; f < 2; ++f)
            #pragma unroll
            for (int j = 0; j < 4; ++j)
                #pragma unroll
                for (int e = 0; e < 4; ++e) acc[f][j][e] = 0.0f;

        const uint32_t aHB = sb + SM_A +            (uint32_t)(mb * PITCHB) + aLaneOff;
        const uint32_t aMB = sb + SM_A + A_TILE +   (uint32_t)(mb * PITCHB) + aLaneOff;
        const uint32_t bHB = sb + bufOff +          (uint32_t)(nb * PITCHB) + bLaneOff;
        const uint32_t bMB = sb + bufOff + B_TILE + (uint32_t)(nb * PITCHB) + bLaneOff;

        #pragma unroll
        for (int ks = 0; ks < 8; ++ks) {
            const uint32_t ko = (uint32_t)(ks * 32);
            uint32_t ah[2][4], am[2][4], bh[2][4], bm[2][4];
            #pragma unroll
            for (int f = 0; f < 2; ++f) {
                ldsm4(ah[f][0], ah[f][1], ah[f][2], ah[f][3],
                      aHB + (uint32_t)(f * 16 * PITCHB) + ko);
                ldsm4(am[f][0], am[f][1], am[f][2], am[f][3],
                      aMB + (uint32_t)(f * 16 * PITCHB) + ko);
            }
            #pragma unroll
            for (int p = 0; p < 2; ++p) {
                ldsm4(bh[p][0], bh[p][1], bh[p][2], bh[p][3],
                      bHB + (uint32_t)(p * 16 * PITCHB) + ko);
                ldsm4(bm[p][0], bm[p][1], bm[p][2], bm[p][3],
                      bMB + (uint32_t)(p * 16 * PITCHB) + ko);
            }

            #pragma unroll
            for (int f = 0; f < 2; ++f)
                #pragma unroll
                for (int p = 0; p < 2; ++p) {
                    // h*m'
                    mma16816(acc[f][p*2+0], ah[f], bm[p][0], bm[p][1]);
                    mma16816(acc[f][p*2+1], ah[f], bm[p][2], bm[p][3]);
                    // m*h'
                    mma16816(acc[f][p*2+0], am[f], bh[p][0], bh[p][1]);
                    mma16816(acc[f][p*2+1], am[f], bh[p][2], bh[p][3]);
                    // h*h'
                    mma16816(acc[f][p*2+0], ah[f], bh[p][0], bh[p][1]);
                    mma16816(acc[f][p*2+1], ah[f], bh[p][2], bh[p][3]);
                }
        }

        // distances + running argmin (ascending n; strict < keeps smallest)
        #pragma unroll
        for (int j = 0; j < 4; ++j)
            #pragma unroll
            for (int e = 0; e < 2; ++e) {
                const int n = c * NCH + nb + j * 8 + c2 + e;
                const float cnv = cnormS[n];
                #pragma unroll
                for (int f = 0; f < 2; ++f)
                    #pragma unroll
                    for (int hh = 0; hh < 2; ++hh) {
                        float s = cnv - 2.0f * acc[f][j][hh * 2 + e];
                        int slot = f * 2 + hh;
                        if (s < bestv[slot]) { bestv[slot] = s; bestn[slot] = n; }
                    }
            }

        __syncthreads();                 // all reads of buf done before overwrite
        if (c + 2 < NCHUNKS)
            prefetchB(k, c + 2, sb + SM_B + (uint32_t)((c & 1) ? B_CHUNK : 0), tid);
        CP_COMMIT();                     // always commit (group accounting)
    }

    // cross-lane reduce within 4-lane column groups, stage per-warp results
    #pragma unroll
    for (int s = 0; s < 4; ++s) {
        float v = bestv[s]; int n = bestn[s];
        #pragma unroll
        for (int off = 1; off <= 2; off <<= 1) {
            float ov = __shfl_xor_sync(0xffffffffu, v, off);
            int   on = __shfl_xor_sync(0xffffffffu, n, off);
            if (ov < v || (ov == v && on < n)) { v = ov; n = on; }
        }
        if ((lane & 3) == 0) {
            int row = mb + (s >> 1) * 16 + (s & 1) * 8 + r4;   // f*16 + hh*8 + r4
            redv[wn * 128 + row] = v;
            redi[wn * 128 + row] = n;
        }
    }
    __syncthreads();

    // final reduce over the 4 n-warps; write indices
    if (tid < 128) {
        float bv = redv[tid]; int bn = redi[tid];
        #pragma unroll
        for (int w = 1; w < 4; ++w) {
            float v = redv[w * 128 + tid]; int n = redi[w * 128 + tid];
            if (v < bv || (v == bv && n < bn)) { bv = v; bn = n; }
        }
        rowIdx[tid] = bn;
        idxOut[((size_t)b * Lq + l0 + tid) * Kq + k] = (float)bn;
    }
    __syncthreads();

    // gather selected fp32 code rows into smem (reuse B region): sel[128][132]
    float* sel = (float*)(smem + SM_B);
    #pragma unroll
    for (int i = 0; i < 8; ++i) {
        int row = wid * 8 + i;
        int idx = rowIdx[row];
        float4 v = *(const float4*)&cb[((size_t)(k * Nq + idx)) * Dq + lane * 4];
        *(float4*)&sel[row * 132 + lane * 4] = v;
    }
    __syncthreads();

    // cumulative output + residual update (coalesced over l)
    {
        const int lR = tid & 127;
        const int d0 = (tid >> 7) * 32;
        size_t outBase  = (((size_t)b * Kq + k) * Dq) * Lq + l0 + lR;
        size_t prevBase = (((size_t)b * Kq + (k - 1)) * Dq) * Lq + l0 + lR;
        size_t resBase  = ((size_t)b * Dq) * Lq + l0 + lR;
        #pragma unroll 4
        for (int dd = 0; dd < 32; ++dd) {
            int d = d0 + dd;
            float code = sel[lR * 132 + d];
            float prev = (k > 0) ? out[prevBase + (size_t)d * Lq] : 0.0f;
            out[outBase + (size_t)d * Lq] = prev + code;
            float ro = (k == 0) ? x[resBase + (size_t)d * Lq]
                                : g_res[resBase + (size_t)d * Lq];
            g_res[resBase + (size_t)d * Lq] = ro - code;
        }
    }
}

extern "C" void kernel_launch(void* const* d_in, const int* in_sizes, int n_in,
                              void* d_out, int out_size)
{
    const float* x  = (const float*)d_in[0];
    const float* cb = (const float*)d_in[1];
    float* out    = (float*)d_out;
    float* idxOut = out + (size_t)ZQ_ELEMS;

    cudaFuncSetAttribute(vq_step, cudaFuncAttributeMaxDynamicSharedMemorySize, SMEM_BYTES);

    cnorm_kernel<<<(Kq * Nq * 32) / 256, 256>>>(cb);
    prep_kernel<<<(Kq * Nq * Dq) / 256, 256>>>(cb);
    for (int k = 0; k < Kq; ++k)
        vq_step<<<dim3(Lq / 128, Bq), THREADS, SMEM_BYTES>>>(x, cb, out, idxOut, k);
}